// round 6
// baseline (speedup 1.0000x reference)
#include <cuda_runtime.h>
#include <cuda_bf16.h>

// TELIF: temporal-encoded LIF neuron scan — single fused kernel.
//   tx : [T, B, N] float32   (T=512, B=64, N=1024)
//   TE : [N, T]    float32
//   out: [T, B, N] float32 spikes
//
// Per (b, n), sequential in t:
//   th = th + v*TE[n,t] - (th - THRESHOLD)*BETA
//   v  = v*DECAY*(1 - y) + x
//   y  = (v > th) ? 1 : 0
//
// TE is staged through shared memory in 32-timestep tiles so the global
// reads are fully coalesced (4 full 128B lines per warp-load) while each
// thread still consumes its own neuron's row (padded smem, conflict-free).

#define T_STEPS 512
#define B_DIM   64
#define N_DIM   1024
#define BN      (B_DIM * N_DIM)      // 65536
#define U       4                    // timesteps per chunk
#define NCHUNK  (T_STEPS / U)        // 128
#define TS_TILE 32                   // timesteps per TE smem tile
#define NTILES  (T_STEPS / TS_TILE)  // 16

#define REST      0.0f
#define DECAY     0.2f
#define THRESHOLD 0.3f
#define BETA      0.02f

// ---- TE tile: global -> registers (coalesced float4) ----------------------
#define LOAD_TE(k)                                                            \
    {                                                                         \
        const float* tep = TE + (size_t)n0 * T_STEPS + (k) * TS_TILE;         \
        _Pragma("unroll")                                                     \
        for (int j = 0; j < 8; j++) {                                         \
            const int idx = j * 64 + (int)threadIdx.x;                        \
            const int row = idx >> 3, c4 = idx & 7;                           \
            ter[j] = *reinterpret_cast<const float4*>(                        \
                tep + (size_t)row * T_STEPS + c4 * 4);                        \
        }                                                                     \
    }

// ---- TE tile: registers -> smem buffer bb ---------------------------------
#define STS_TE(bb)                                                            \
    {                                                                         \
        _Pragma("unroll")                                                     \
        for (int j = 0; j < 8; j++) {                                         \
            const int idx = j * 64 + (int)threadIdx.x;                        \
            const int row = idx >> 3, c4 = idx & 7;                           \
            te_s[bb][row][c4 * 4 + 0] = ter[j].x;                             \
            te_s[bb][row][c4 * 4 + 1] = ter[j].y;                             \
            te_s[bb][row][c4 * 4 + 2] = ter[j].z;                             \
            te_s[bb][row][c4 * 4 + 3] = ter[j].w;                             \
        }                                                                     \
    }

// ---- tx chunk prefetch (streaming) ----------------------------------------
#define TXLOAD(xq, c)                                                         \
    {                                                                         \
        _Pragma("unroll")                                                     \
        for (int u = 0; u < U; u++)                                           \
            xq[u] = __ldcs(&tx[((size_t)(c) * U + u) * BN + g]);              \
    }

// ---- one timestep (arithmetic form identical to the rel_err==0.0 version) -
#define ONE_STEP(x, te, c, u)                                                 \
    {                                                                         \
        th = th + v * (te) - (th - THRESHOLD) * BETA;                         \
        v  = v * DECAY * (1.0f - y) + (x);                                    \
        y  = (v > th) ? 1.0f : 0.0f;                                          \
        __stcs(&ty[((size_t)(c) * U + (u)) * BN + g], y);                     \
    }

// ---- one chunk: TE from smem (conflict-free), spikes out ------------------
#define COMPUTE_CHUNK(xq, bb, iloc, c)                                        \
    {                                                                         \
        const float* terow = &te_s[bb][threadIdx.x][(iloc) * U];              \
        ONE_STEP(xq[0], terow[0], c, 0)                                       \
        ONE_STEP(xq[1], terow[1], c, 1)                                       \
        ONE_STEP(xq[2], terow[2], c, 2)                                       \
        ONE_STEP(xq[3], terow[3], c, 3)                                       \
    }

__global__ void __launch_bounds__(64) telif_kernel(
    const float* __restrict__ tx,
    const float* __restrict__ TE,
    float* __restrict__ ty)
{
    __shared__ float te_s[2][64][33];   // padded: LDS bank = (tid + t) % 32

    const int g  = blockIdx.x * 64 + threadIdx.x;    // g = b*N + n
    const int n0 = (blockIdx.x & (N_DIM / 64 - 1)) * 64;  // block's n origin

    float v  = REST;
    float y  = 0.0f;
    float th = THRESHOLD;

    float4 ter[8];                       // TE staging (next tile)
    float  x0[U], x1[U], x2[U], x3[U];   // tx pipeline, distance 4 chunks

    // prologue
    LOAD_TE(0)
    STS_TE(0)
    TXLOAD(x0, 0) TXLOAD(x1, 1) TXLOAD(x2, 2) TXLOAD(x3, 3)
    __syncthreads();
    LOAD_TE(1)

    #pragma unroll 1
    for (int tile = 0; tile < NTILES; tile++) {
        const int b  = tile & 1;
        const int c0 = tile * 8;

        COMPUTE_CHUNK(x0, b, 0, c0 + 0) if (c0 + 4  < NCHUNK) TXLOAD(x0, c0 + 4)
        COMPUTE_CHUNK(x1, b, 1, c0 + 1) if (c0 + 5  < NCHUNK) TXLOAD(x1, c0 + 5)
        COMPUTE_CHUNK(x2, b, 2, c0 + 2) if (c0 + 6  < NCHUNK) TXLOAD(x2, c0 + 6)
        COMPUTE_CHUNK(x3, b, 3, c0 + 3) if (c0 + 7  < NCHUNK) TXLOAD(x3, c0 + 7)
        COMPUTE_CHUNK(x0, b, 4, c0 + 4) if (c0 + 8  < NCHUNK) TXLOAD(x0, c0 + 8)
        COMPUTE_CHUNK(x1, b, 5, c0 + 5) if (c0 + 9  < NCHUNK) TXLOAD(x1, c0 + 9)
        COMPUTE_CHUNK(x2, b, 6, c0 + 6) if (c0 + 10 < NCHUNK) TXLOAD(x2, c0 + 10)
        COMPUTE_CHUNK(x3, b, 7, c0 + 7) if (c0 + 11 < NCHUNK) TXLOAD(x3, c0 + 11)

        if (tile + 1 < NTILES) {
            STS_TE(b ^ 1)                 // publish next tile's TE
            __syncthreads();              // safe: 2 buffers, 1 barrier/tile
            if (tile + 2 < NTILES) LOAD_TE(tile + 2)   // hide global latency
        }
    }
}

// ---------------------------------------------------------------------------
extern "C" void kernel_launch(void* const* d_in, const int* in_sizes, int n_in,
                              void* d_out, int out_size) {
    const float* tx = (const float*)d_in[0];   // [T, B, N]
    const float* TE = (const float*)d_in[1];   // [N, T]
    float* ty = (float*)d_out;                 // [T, B, N]
    (void)in_sizes; (void)n_in; (void)out_size;

    telif_kernel<<<BN / 64, 64>>>(tx, TE, ty);
}